// round 10
// baseline (speedup 1.0000x reference)
#include <cuda_runtime.h>
#include <cuda_bf16.h>
#include <cstdint>

#define BB   8192
#define TT   64
#define FF   64
#define ORD  16
#define KK   256            // hidden units
#define RTOT 336            // F + ORD + K
#define NCH  21             // 336/16 k-chunks
#define MT   64             // rows per CTA
#define NT   256            // z-cols per CTA (64 units * 4 gates)
#define NTH  512

// smem: staged tiles, rows padded to 48B for conflict-free ldmatrix
#define ROWB   48
#define OFF_AH 0
#define OFF_AL (64 * ROWB)             // 3072
#define OFF_WH (2 * 64 * ROWB)         // 6144
#define OFF_WL (OFF_WH + 256 * ROWB)   // 18432
#define BUFSZ  (OFF_WL + 256 * ROWB)   // 30720
#define OFF_PART (2 * BUFSZ)           // 61440, 64x8 floats
#define SMEM_TOTAL (OFF_PART + 64 * 8 * 4 + 256)

// ---------------- persistent device state ----------------
__device__ __align__(16) __nv_bfloat16 g_Xh[(size_t)BB * TT * FF];
__device__ __align__(16) __nv_bfloat16 g_Xl[(size_t)BB * TT * FF];
__device__ __align__(16) __nv_bfloat16 g_Hh[2][(size_t)BB * KK];
__device__ __align__(16) __nv_bfloat16 g_Hl[2][(size_t)BB * KK];
__device__ __align__(16) float g_c[(size_t)BB * KK];
__device__ __align__(16) __nv_bfloat16 g_YPh[BB * ORD];
__device__ __align__(16) __nv_bfloat16 g_YPl[BB * ORD];
__device__ __align__(16) __nv_bfloat16 g_Wth[1024 * RTOT];   // [n'=4u+g][k]
__device__ __align__(16) __nv_bfloat16 g_Wtl[1024 * RTOT];
__device__ float4 g_biasp[KK];
__device__ float  g_part[4 * BB];      // per-col-CTA partial dense dots

// ---------------- helpers ----------------
__device__ __forceinline__ uint32_t smem_u32(const void* p) {
    uint32_t a;
    asm("{ .reg .u64 t; cvta.to.shared.u64 t, %1; cvt.u32.u64 %0, t; }" : "=r"(a) : "l"(p));
    return a;
}
__device__ __forceinline__ void cpa16(uint32_t dst, const void* src) {
    asm volatile("cp.async.cg.shared.global [%0], [%1], 16;" :: "r"(dst), "l"(src) : "memory");
}
__device__ __forceinline__ void ldsm4(uint32_t (&r)[4], uint32_t a) {
    asm volatile("ldmatrix.sync.aligned.m8n8.x4.shared.b16 {%0,%1,%2,%3}, [%4];"
                 : "=r"(r[0]), "=r"(r[1]), "=r"(r[2]), "=r"(r[3]) : "r"(a));
}
__device__ __forceinline__ void mma16816(float (&d)[4], const uint32_t (&a)[4],
                                         uint32_t b0, uint32_t b1) {
    asm volatile("mma.sync.aligned.m16n8k16.row.col.f32.bf16.bf16.f32 "
                 "{%0,%1,%2,%3}, {%4,%5,%6,%7}, {%8,%9}, {%0,%1,%2,%3};"
                 : "+f"(d[0]), "+f"(d[1]), "+f"(d[2]), "+f"(d[3])
                 : "r"(a[0]), "r"(a[1]), "r"(a[2]), "r"(a[3]), "r"(b0), "r"(b1));
}
__device__ __forceinline__ float sigm(float x) { return 1.0f / (1.0f + __expf(-x)); }
__device__ __forceinline__ float tanh_(float x) {
    float e = __expf(2.0f * x);
    return 1.0f - 2.0f / (e + 1.0f);
}
__device__ __forceinline__ void split_bf16(float v, __nv_bfloat16& hi, __nv_bfloat16& lo) {
    hi = __float2bfloat16(v);
    lo = __float2bfloat16(v - __bfloat162float(hi));
}

// ---------------- setup kernels ----------------
__global__ void conv_x_kernel(const float* __restrict__ x) {
    size_t n = (size_t)BB * TT * FF;
    for (size_t i = (size_t)blockIdx.x * blockDim.x + threadIdx.x; i < n;
         i += (size_t)gridDim.x * blockDim.x) {
        __nv_bfloat16 h, l;
        split_bf16(x[i], h, l);
        g_Xh[i] = h; g_Xl[i] = l;
    }
}
__global__ void init_state_kernel(const float* __restrict__ y0) {
    int i = blockIdx.x * blockDim.x + threadIdx.x;
    int st = gridDim.x * blockDim.x;
    __nv_bfloat16 z = __float2bfloat16(0.0f);
    for (size_t s = i; s < (size_t)BB * KK; s += st) {
        g_c[s] = 0.0f;
        g_Hh[0][s] = z; g_Hl[0][s] = z;
        g_Hh[1][s] = z; g_Hl[1][s] = z;
    }
    for (int s = i; s < BB * ORD; s += st) {
        __nv_bfloat16 h, l;
        split_bf16(y0[s], h, l);
        g_YPh[s] = h; g_YPl[s] = l;
    }
}
__global__ void repack_w_kernel(const float* __restrict__ kern,  // [80,1024]
                                const float* __restrict__ rec,   // [256,1024]
                                const float* __restrict__ bias) {
    int i = blockIdx.x * blockDim.x + threadIdx.x;
    int st = gridDim.x * blockDim.x;
    for (int idx = i; idx < 1024 * RTOT; idx += st) {
        int np = idx / RTOT;
        int k  = idx - np * RTOT;
        int u = np >> 2, g = np & 3;
        int col = g * 256 + u;                  // Keras gate order i,f,c,o
        float v = (k < FF + ORD) ? kern[k * 1024 + col] : rec[(k - 80) * 1024 + col];
        __nv_bfloat16 h, l;
        split_bf16(v, h, l);
        g_Wth[idx] = h; g_Wtl[idx] = l;
    }
    for (int u = i; u < KK; u += st) {
        float4 b;
        b.x = bias[u]; b.y = bias[256 + u]; b.z = bias[512 + u]; b.w = bias[768 + u];
        g_biasp[u] = b;
    }
}

// ---------------- fused timestep: HMMA GEMM + gates + partial dense ---------
// grid (128, 4), 512 threads. Warp tile 32 rows x 32 cols. acc fp32 (32 regs).
__global__ void __launch_bounds__(NTH, 1)
lstm_step(int t, int par, const float* __restrict__ dw) {
    extern __shared__ __align__(16) char sm[];
    const uint32_t sb = smem_u32(sm);
    const int tid  = threadIdx.x;
    const int wid  = tid >> 5;
    const int lane = tid & 31;
    const int g8   = lane >> 2;
    const int tid4 = lane & 3;
    const int warpM = wid & 1;       // 2 row groups * 32 rows
    const int warpN = wid >> 1;      // 8 col groups * 32 cols
    const int mrow0 = blockIdx.x * MT;
    const int ncol0 = blockIdx.y * NT;

    // ---- hoisted staging source pointers ----
    // A: threads 0..255 stage; job = tid: row=tid>>2, half=tid&1, hilo=(tid>>1)&1
    const int a_row  = tid >> 2;
    const int a_half = tid & 1;
    const int a_hilo = (tid >> 1) & 1;
    const int a_grow = mrow0 + a_row;
    const __nv_bfloat16* aX = (a_hilo ? g_Xl : g_Xh) +
        (size_t)a_grow * (TT * FF) + (size_t)t * FF + a_half * 8;
    const __nv_bfloat16* aY = (a_hilo ? g_YPl : g_YPh) + a_grow * ORD + a_half * 8;
    const __nv_bfloat16* aH = (a_hilo ? g_Hl[par] : g_Hh[par]) +
        (size_t)a_grow * KK + a_half * 8;
    const uint32_t a_dst = (a_hilo ? OFF_AL : OFF_AH) + a_row * ROWB + a_half * 16;

    // W: 2 jobs per thread
    const __nv_bfloat16* wsrc[2];
    uint32_t wdst[2];
    #pragma unroll
    for (int j = 0; j < 2; j++) {
        int idx  = tid + j * NTH;
        int n    = idx >> 2;
        int half = idx & 1;
        int hilo = (idx >> 1) & 1;
        wsrc[j] = (hilo ? g_Wtl : g_Wth) + (size_t)(ncol0 + n) * RTOT + half * 8;
        wdst[j] = (hilo ? OFF_WL : OFF_WH) + n * ROWB + half * 16;
    }

    auto stage = [&](int kc, int b) {
        const uint32_t bufb = sb + b * BUFSZ;
        if (tid < 256) {
            const __nv_bfloat16* src;
            if (kc < 4)       src = aX + kc * 16;
            else if (kc == 4) src = aY;
            else              src = aH + (kc - 5) * 16;
            cpa16(bufb + a_dst, src);
        }
        #pragma unroll
        for (int j = 0; j < 2; j++)
            cpa16(bufb + wdst[j], wsrc[j] + kc * 16);
        asm volatile("cp.async.commit_group;" ::: "memory");
    };

    float acc[2][4][4];   // [mi][nj(8col)][quad] = 32 regs
    #pragma unroll
    for (int mi = 0; mi < 2; mi++)
        #pragma unroll
        for (int nj = 0; nj < 4; nj++)
            #pragma unroll
            for (int q = 0; q < 4; q++) acc[mi][nj][q] = 0.0f;

    stage(0, 0);
    const int lrow = lane & 15;
    const int lcol16 = (lane >> 4) * 16;
    const uint32_t aoff = (uint32_t)(warpM * 32 + lrow) * ROWB + lcol16;
    const uint32_t woff = (uint32_t)(warpN * 32 + lrow) * ROWB + lcol16;

    for (int kc = 0; kc < NCH; kc++) {
        if (kc + 1 < NCH) {
            stage(kc + 1, (kc + 1) & 1);
            asm volatile("cp.async.wait_group 1;" ::: "memory");
        } else {
            asm volatile("cp.async.wait_group 0;" ::: "memory");
        }
        __syncthreads();

        const uint32_t bufb = sb + (kc & 1) * BUFSZ;
        uint32_t ah[2][4], al[2][4];
        #pragma unroll
        for (int mi = 0; mi < 2; mi++) {
            ldsm4(ah[mi], bufb + OFF_AH + aoff + mi * (16 * ROWB));
            ldsm4(al[mi], bufb + OFF_AL + aoff + mi * (16 * ROWB));
        }
        #pragma unroll
        for (int nb = 0; nb < 2; nb++) {
            uint32_t wh[4], wl[4];
            ldsm4(wh, bufb + OFF_WH + woff + nb * (16 * ROWB));
            ldsm4(wl, bufb + OFF_WL + woff + nb * (16 * ROWB));
            #pragma unroll
            for (int mi = 0; mi < 2; mi++) {
                mma16816(acc[mi][2 * nb + 0], ah[mi], wh[0], wh[2]);
                mma16816(acc[mi][2 * nb + 1], ah[mi], wh[1], wh[3]);
                mma16816(acc[mi][2 * nb + 0], al[mi], wh[0], wh[2]);
                mma16816(acc[mi][2 * nb + 1], al[mi], wh[1], wh[3]);
                mma16816(acc[mi][2 * nb + 0], ah[mi], wl[0], wl[2]);
                mma16816(acc[mi][2 * nb + 1], ah[mi], wl[1], wl[3]);
            }
        }
        __syncthreads();
    }

    // ---- epilogue: gates, state update, partial dense dot ----
    __nv_bfloat16* __restrict__ Hho = g_Hh[par ^ 1];
    __nv_bfloat16* __restrict__ Hlo = g_Hl[par ^ 1];
    float rd[4] = {0.0f, 0.0f, 0.0f, 0.0f};
    const bool evenlane = ((tid4 & 1) == 0);

    #pragma unroll
    for (int mi = 0; mi < 2; mi++) {
        #pragma unroll
        for (int nj = 0; nj < 4; nj++) {
            float c0 = acc[mi][nj][0], c1 = acc[mi][nj][1];
            float c2 = acc[mi][nj][2], c3 = acc[mi][nj][3];
            float o0 = __shfl_xor_sync(0xffffffffu, c0, 1);
            float o1 = __shfl_xor_sync(0xffffffffu, c1, 1);
            float o2 = __shfl_xor_sync(0xffffffffu, c2, 1);
            float o3 = __shfl_xor_sync(0xffffffffu, c3, 1);
            if (evenlane) {
                const int u = ((ncol0 + warpN * 32 + nj * 8) >> 2) + (tid4 >> 1);
                const float4 bp = g_biasp[u];
                const float dwu = dw[u];
                const int r0 = mrow0 + warpM * 32 + mi * 16 + g8;
                #pragma unroll
                for (int rr = 0; rr < 2; rr++) {
                    const float zi = rr ? c2 : c0;
                    const float zf = rr ? c3 : c1;
                    const float zg = rr ? o2 : o0;
                    const float zo = rr ? o3 : o1;
                    const int row = r0 + rr * 8;
                    const size_t off = (size_t)row * KK + u;
                    float gi = sigm(zi + bp.x);
                    float gf = sigm(zf + bp.y);
                    float gg = tanh_(zg + bp.z);
                    float go = sigm(zo + bp.w);
                    float cn = gf * g_c[off] + gi * gg;
                    g_c[off] = cn;
                    float hn = go * tanh_(cn);
                    __nv_bfloat16 hh, hl;
                    split_bf16(hn, hh, hl);
                    Hho[off] = hh;
                    Hlo[off] = hl;
                    rd[mi * 2 + rr] += hn * dwu;
                }
            }
        }
    }
    #pragma unroll
    for (int q = 0; q < 4; q++)
        rd[q] += __shfl_xor_sync(0xffffffffu, rd[q], 2);

    float* part = (float*)(sm + OFF_PART);   // [64][8]
    if (tid4 == 0) {
        #pragma unroll
        for (int mi = 0; mi < 2; mi++)
            #pragma unroll
            for (int rr = 0; rr < 2; rr++)
                part[(warpM * 32 + mi * 16 + g8 + rr * 8) * 8 + warpN] = rd[mi * 2 + rr];
    }
    __syncthreads();
    if (tid < 64) {
        const float* pr = part + tid * 8;
        float s = pr[0] + pr[1] + pr[2] + pr[3] + pr[4] + pr[5] + pr[6] + pr[7];
        g_part[blockIdx.y * BB + mrow0 + tid] = s;
    }
}

// ---------------- finalize: sum partials, emit pred, shift window -----------
__global__ void finalize_kernel(float* __restrict__ out,
                                const float* __restrict__ db, int t) {
    const int row = blockIdx.x * blockDim.x + threadIdx.x;
    if (row >= BB) return;
    float p = g_part[row] + g_part[BB + row] + g_part[2 * BB + row] +
              g_part[3 * BB + row] + db[0];
    out[(size_t)row * TT + t] = p;

    __nv_bfloat16* yph = g_YPh + row * ORD;
    __nv_bfloat16* ypl = g_YPl + row * ORD;
    __nv_bfloat16 th[ORD], tl[ORD];
    #pragma unroll
    for (int i = 0; i < ORD; i++) { th[i] = yph[i]; tl[i] = ypl[i]; }
    #pragma unroll
    for (int i = ORD - 1; i >= 1; i--) { yph[i] = th[i - 1]; ypl[i] = tl[i - 1]; }
    __nv_bfloat16 ph, pl;
    split_bf16(p, ph, pl);
    yph[0] = ph; ypl[0] = pl;
}

// ---------------- launch ----------------
extern "C" void kernel_launch(void* const* d_in, const int* in_sizes, int n_in,
                              void* d_out, int out_size) {
    const float* x    = (const float*)d_in[0];
    const float* y0   = (const float*)d_in[1];
    const float* kern = (const float*)d_in[2];
    const float* rec  = (const float*)d_in[3];
    const float* bias = (const float*)d_in[4];
    const float* dw   = (const float*)d_in[5];
    const float* db   = (const float*)d_in[6];
    float* out = (float*)d_out;

    cudaFuncSetAttribute(lstm_step,
                         cudaFuncAttributeMaxDynamicSharedMemorySize, SMEM_TOTAL);

    conv_x_kernel<<<2048, 256>>>(x);
    init_state_kernel<<<1024, 256>>>(y0);
    repack_w_kernel<<<1024, 256>>>(kern, rec, bias);

    dim3 grid(BB / MT, 4);   // (128, 4)
    for (int t = 0; t < TT; t++) {
        lstm_step<<<grid, NTH, SMEM_TOTAL>>>(t, t & 1, dw);
        finalize_kernel<<<BB / 256, 256>>>(out, db, t);
    }
}

// round 11
// speedup vs baseline: 1.4626x; 1.4626x over previous
#include <cuda_runtime.h>
#include <cuda_fp16.h>
#include <cstdint>

#define BB   8192
#define TT   64
#define FF   64
#define ORD  16
#define KK   256            // hidden units
#define RTOT 336            // F + ORD + K
#define NCH  21             // 336/16 k-chunks
#define MT   128            // rows per CTA
#define NT   256            // z-cols per CTA (64 units * 4 gates)
#define NTH  512

// smem: staged tiles, rows padded to 48B for conflict-free ldmatrix
#define ROWB   48
#define OFF_AH 0
#define OFF_AL (128 * ROWB)            // 6144
#define OFF_WH (2 * 128 * ROWB)        // 12288
#define BUFSZ  (OFF_WH + 256 * ROWB)   // 24576
#define OFF_PART (2 * BUFSZ)           // 49152, 128x4 floats
#define SMEM_TOTAL (OFF_PART + 128 * 4 * 4 + 256)

// ---------------- persistent device state ----------------
__device__ __align__(16) __half g_Xh[(size_t)BB * TT * FF];
__device__ __align__(16) __half g_Xl[(size_t)BB * TT * FF];
__device__ __align__(16) __half g_Hh[2][(size_t)BB * KK];
__device__ __align__(16) __half g_Hl[2][(size_t)BB * KK];
__device__ __align__(16) float g_c[(size_t)BB * KK];
__device__ __align__(16) __half g_YPh[BB * ORD];
__device__ __align__(16) __half g_YPl[BB * ORD];
__device__ __align__(16) __half g_Wth[1024 * RTOT];   // [n'=4u+g][k], fp16-rounded W
__device__ float4 g_biasp[KK];
__device__ float  g_part[4 * BB];      // per-col-CTA partial dense dots

// ---------------- helpers ----------------
__device__ __forceinline__ uint32_t smem_u32(const void* p) {
    uint32_t a;
    asm("{ .reg .u64 t; cvta.to.shared.u64 t, %1; cvt.u32.u64 %0, t; }" : "=r"(a) : "l"(p));
    return a;
}
__device__ __forceinline__ void cpa16(uint32_t dst, const void* src) {
    asm volatile("cp.async.cg.shared.global [%0], [%1], 16;" :: "r"(dst), "l"(src) : "memory");
}
__device__ __forceinline__ void ldsm4(uint32_t (&r)[4], uint32_t a) {
    asm volatile("ldmatrix.sync.aligned.m8n8.x4.shared.b16 {%0,%1,%2,%3}, [%4];"
                 : "=r"(r[0]), "=r"(r[1]), "=r"(r[2]), "=r"(r[3]) : "r"(a));
}
__device__ __forceinline__ void mma16816(float (&d)[4], const uint32_t (&a)[4],
                                         uint32_t b0, uint32_t b1) {
    asm volatile("mma.sync.aligned.m16n8k16.row.col.f32.f16.f16.f32 "
                 "{%0,%1,%2,%3}, {%4,%5,%6,%7}, {%8,%9}, {%0,%1,%2,%3};"
                 : "+f"(d[0]), "+f"(d[1]), "+f"(d[2]), "+f"(d[3])
                 : "r"(a[0]), "r"(a[1]), "r"(a[2]), "r"(a[3]), "r"(b0), "r"(b1));
}
__device__ __forceinline__ float sigm(float x) { return 1.0f / (1.0f + __expf(-x)); }
__device__ __forceinline__ float tanh_(float x) {
    float e = __expf(2.0f * x);
    return 1.0f - 2.0f / (e + 1.0f);
}
__device__ __forceinline__ void split_h(float v, __half& hi, __half& lo) {
    hi = __float2half_rn(v);
    lo = __float2half_rn(v - __half2float(hi));
}

// ---------------- setup kernels ----------------
__global__ void conv_x_kernel(const float* __restrict__ x) {
    size_t n = (size_t)BB * TT * FF;
    for (size_t i = (size_t)blockIdx.x * blockDim.x + threadIdx.x; i < n;
         i += (size_t)gridDim.x * blockDim.x) {
        __half h, l;
        split_h(x[i], h, l);
        g_Xh[i] = h; g_Xl[i] = l;
    }
}
__global__ void init_state_kernel(const float* __restrict__ y0) {
    int i = blockIdx.x * blockDim.x + threadIdx.x;
    int st = gridDim.x * blockDim.x;
    __half z = __float2half_rn(0.0f);
    for (size_t s = i; s < (size_t)BB * KK; s += st) {
        g_c[s] = 0.0f;
        g_Hh[0][s] = z; g_Hl[0][s] = z;
        g_Hh[1][s] = z; g_Hl[1][s] = z;
    }
    for (int s = i; s < BB * ORD; s += st) {
        __half h, l;
        split_h(y0[s], h, l);
        g_YPh[s] = h; g_YPl[s] = l;
    }
}
__global__ void repack_w_kernel(const float* __restrict__ kern,  // [80,1024]
                                const float* __restrict__ rec,   // [256,1024]
                                const float* __restrict__ bias) {
    int i = blockIdx.x * blockDim.x + threadIdx.x;
    int st = gridDim.x * blockDim.x;
    for (int idx = i; idx < 1024 * RTOT; idx += st) {
        int np = idx / RTOT;
        int k  = idx - np * RTOT;
        int u = np >> 2, g = np & 3;
        int col = g * 256 + u;                  // Keras gate order i,f,c,o
        float v = (k < FF + ORD) ? kern[k * 1024 + col] : rec[(k - 80) * 1024 + col];
        g_Wth[idx] = __float2half_rn(v);
    }
    for (int u = i; u < KK; u += st) {
        float4 b;
        b.x = bias[u]; b.y = bias[256 + u]; b.z = bias[512 + u]; b.w = bias[768 + u];
        g_biasp[u] = b;
    }
}

// ---------------- fused timestep: HMMA GEMM + gates + partial dense ---------
// grid (64, 4), 512 threads. Warp tile 32 rows x 64 cols. acc fp32.
// z = (Ah + Al) * Wh : A exact via fp16 hi/lo, W rounded to fp16 once.
__global__ void __launch_bounds__(NTH, 1)
lstm_step(int t, int par, const float* __restrict__ dw) {
    extern __shared__ __align__(16) char sm[];
    const uint32_t sb = smem_u32(sm);
    const int tid  = threadIdx.x;
    const int wid  = tid >> 5;
    const int lane = tid & 31;
    const int g8   = lane >> 2;      // groupID (row within m16 half)
    const int tid4 = lane & 3;
    const int warpM = wid & 3;       // 4 row groups * 32 rows
    const int warpN = wid >> 2;      // 4 col groups * 64 cols
    const int mrow0 = blockIdx.x * MT;
    const int ncol0 = blockIdx.y * NT;

    const __half* __restrict__ Hh = g_Hh[par];
    const __half* __restrict__ Hl = g_Hl[par];

    // --- staging: one k16 chunk into buffer b ---
    auto stage = [&](int kc, int b) {
        uint32_t bufb = sb + b * BUFSZ;
        // A: 128 rows x {hi,lo} x {k8 halves} = 512 jobs, 1 per thread
        {
            int row  = tid >> 2;
            int half = tid & 1;
            int hilo = (tid >> 1) & 1;
            int kg   = kc * 16 + half * 8;
            int grow = mrow0 + row;
            const __half* src;
            if (kg < 64)
                src = (hilo ? g_Xl : g_Xh) + (size_t)grow * (TT * FF) + t * FF + kg;
            else if (kg < 80)
                src = (hilo ? g_YPl : g_YPh) + grow * ORD + (kg - 64);
            else
                src = (hilo ? Hl : Hh) + (size_t)grow * KK + (kg - 80);
            cpa16(bufb + (hilo ? OFF_AL : OFF_AH) + row * ROWB + half * 16, src);
        }
        // W hi only: 256 n-rows x {halves} = 512 jobs, 1 per thread
        {
            int n    = tid >> 1;
            int half = tid & 1;
            const __half* src =
                g_Wth + (size_t)(ncol0 + n) * RTOT + kc * 16 + half * 8;
            cpa16(bufb + OFF_WH + n * ROWB + half * 16, src);
        }
        asm volatile("cp.async.commit_group;" ::: "memory");
    };

    float acc[2][8][4];
    #pragma unroll
    for (int mi = 0; mi < 2; mi++)
        #pragma unroll
        for (int nj = 0; nj < 8; nj++)
            #pragma unroll
            for (int q = 0; q < 4; q++) acc[mi][nj][q] = 0.0f;

    stage(0, 0);
    const int lrow = lane & 15;            // ldmatrix row-in-tile
    const int lcol16 = (lane >> 4) * 16;   // ldmatrix 16B column half
    const uint32_t aoff = (uint32_t)(warpM * 32 + lrow) * ROWB + lcol16;
    const uint32_t woff = (uint32_t)(warpN * 64 + lrow) * ROWB + lcol16;

    for (int kc = 0; kc < NCH; kc++) {
        if (kc + 1 < NCH) {
            stage(kc + 1, (kc + 1) & 1);
            asm volatile("cp.async.wait_group 1;" ::: "memory");
        } else {
            asm volatile("cp.async.wait_group 0;" ::: "memory");
        }
        __syncthreads();

        const uint32_t bufb = sb + (kc & 1) * BUFSZ;
        uint32_t ah[2][4], al[2][4];
        #pragma unroll
        for (int mi = 0; mi < 2; mi++) {
            ldsm4(ah[mi], bufb + OFF_AH + aoff + mi * (16 * ROWB));
            ldsm4(al[mi], bufb + OFF_AL + aoff + mi * (16 * ROWB));
        }
        #pragma unroll
        for (int nb = 0; nb < 4; nb++) {
            uint32_t wh[4];
            ldsm4(wh, bufb + OFF_WH + woff + nb * (16 * ROWB));
            #pragma unroll
            for (int mi = 0; mi < 2; mi++) {
                mma16816(acc[mi][2 * nb + 0], ah[mi], wh[0], wh[2]);
                mma16816(acc[mi][2 * nb + 1], ah[mi], wh[1], wh[3]);
                mma16816(acc[mi][2 * nb + 0], al[mi], wh[0], wh[2]);
                mma16816(acc[mi][2 * nb + 1], al[mi], wh[1], wh[3]);
            }
        }
        __syncthreads();
    }

    // ---- epilogue: gates, state update, partial dense dot ----
    __half* __restrict__ Hho = g_Hh[par ^ 1];
    __half* __restrict__ Hlo = g_Hl[par ^ 1];
    float rd[4] = {0.0f, 0.0f, 0.0f, 0.0f};
    const bool evenlane = ((tid4 & 1) == 0);

    #pragma unroll
    for (int mi = 0; mi < 2; mi++) {
        #pragma unroll
        for (int nj = 0; nj < 8; nj++) {
            float c0 = acc[mi][nj][0], c1 = acc[mi][nj][1];
            float c2 = acc[mi][nj][2], c3 = acc[mi][nj][3];
            float o0 = __shfl_xor_sync(0xffffffffu, c0, 1);
            float o1 = __shfl_xor_sync(0xffffffffu, c1, 1);
            float o2 = __shfl_xor_sync(0xffffffffu, c2, 1);
            float o3 = __shfl_xor_sync(0xffffffffu, c3, 1);
            if (evenlane) {
                const int u = ((ncol0 + warpN * 64 + nj * 8) >> 2) + (tid4 >> 1);
                const float4 bp = g_biasp[u];
                const float dwu = dw[u];
                const int r0 = mrow0 + warpM * 32 + mi * 16 + g8;
                #pragma unroll
                for (int rr = 0; rr < 2; rr++) {
                    const float zi = rr ? c2 : c0;
                    const float zf = rr ? c3 : c1;
                    const float zg = rr ? o2 : o0;
                    const float zo = rr ? o3 : o1;
                    const int row = r0 + rr * 8;
                    const size_t off = (size_t)row * KK + u;
                    float gi = sigm(zi + bp.x);
                    float gf = sigm(zf + bp.y);
                    float gg = tanh_(zg + bp.z);
                    float go = sigm(zo + bp.w);
                    float cn = gf * g_c[off] + gi * gg;
                    g_c[off] = cn;
                    float hn = go * tanh_(cn);
                    __half hh, hl;
                    split_h(hn, hh, hl);
                    Hho[off] = hh;
                    Hlo[off] = hl;
                    rd[mi * 2 + rr] += hn * dwu;
                }
            }
        }
    }
    // combine tid4 0<->2
    #pragma unroll
    for (int q = 0; q < 4; q++)
        rd[q] += __shfl_xor_sync(0xffffffffu, rd[q], 2);

    float* part = (float*)(sm + OFF_PART);   // [128][4]
    if (tid4 == 0) {
        #pragma unroll
        for (int mi = 0; mi < 2; mi++)
            #pragma unroll
            for (int rr = 0; rr < 2; rr++)
                part[(warpM * 32 + mi * 16 + g8 + rr * 8) * 4 + warpN] = rd[mi * 2 + rr];
    }
    __syncthreads();
    if (tid < 128) {
        float s = part[tid * 4 + 0] + part[tid * 4 + 1] +
                  part[tid * 4 + 2] + part[tid * 4 + 3];
        g_part[blockIdx.y * BB + mrow0 + tid] = s;
    }
}

// ---------------- finalize: sum partials, emit pred, shift window -----------
__global__ void finalize_kernel(float* __restrict__ out,
                                const float* __restrict__ db, int t) {
    const int row = blockIdx.x * blockDim.x + threadIdx.x;
    if (row >= BB) return;
    float p = g_part[row] + g_part[BB + row] + g_part[2 * BB + row] +
              g_part[3 * BB + row] + db[0];
    out[(size_t)row * TT + t] = p;

    __half* yph = g_YPh + row * ORD;
    __half* ypl = g_YPl + row * ORD;
    __half th[ORD], tl[ORD];
    #pragma unroll
    for (int i = 0; i < ORD; i++) { th[i] = yph[i]; tl[i] = ypl[i]; }
    #pragma unroll
    for (int i = ORD - 1; i >= 1; i--) { yph[i] = th[i - 1]; ypl[i] = tl[i - 1]; }
    __half ph, pl;
    split_h(p, ph, pl);
    yph[0] = ph; ypl[0] = pl;
}

// ---------------- launch ----------------
extern "C" void kernel_launch(void* const* d_in, const int* in_sizes, int n_in,
                              void* d_out, int out_size) {
    const float* x    = (const float*)d_in[0];
    const float* y0   = (const float*)d_in[1];
    const float* kern = (const float*)d_in[2];
    const float* rec  = (const float*)d_in[3];
    const float* bias = (const float*)d_in[4];
    const float* dw   = (const float*)d_in[5];
    const float* db   = (const float*)d_in[6];
    float* out = (float*)d_out;

    cudaFuncSetAttribute(lstm_step,
                         cudaFuncAttributeMaxDynamicSharedMemorySize, SMEM_TOTAL);

    conv_x_kernel<<<2048, 256>>>(x);
    init_state_kernel<<<1024, 256>>>(y0);
    repack_w_kernel<<<1024, 256>>>(kern, rec, bias);

    dim3 grid(BB / MT, 4);   // (64, 4)
    for (int t = 0; t < TT; t++) {
        lstm_step<<<grid, NTH, SMEM_TOTAL>>>(t, t & 1, dw);
        finalize_kernel<<<BB / 256, 256>>>(out, db, t);
    }
}